// round 6
// baseline (speedup 1.0000x reference)
#include <cuda_runtime.h>
#include <math.h>

#define NE   800000
#define NND  100000
#define HH   128
#define KIN  256          // H + IN
#define FF   512          // 4*H
#define TE   128          // edges/nodes per block tile
#define KC   32           // K chunk
#define LDT  (TE + 4)     // padded SMEM stride (132)
#define SINV (1.0f/30.0f)

// scratch: aggregated messages (dh). 100000*128*4 = 51.2 MB
__device__ float g_dh[(size_t)NND * HH];

// ---------------------------------------------------------------------------
__global__ void zero_dh_kernel() {
    size_t i = (size_t)blockIdx.x * blockDim.x + threadIdx.x;
    if (i < (size_t)NND * HH / 4)
        ((float4*)g_dh)[i] = make_float4(0.f, 0.f, 0.f, 0.f);
}

// ---------------------------------------------------------------------------
// Fused edge MLP: msg = W3(relu(W2(relu(W1 x + b1)) + b2)) + b3, then
// atomic scatter msg/SCALE into g_dh[src].
// Per block: 128 edges, 256 threads, each thread owns an 8x8 micro-tile.
__global__ __launch_bounds__(256, 1)
void edge_kernel(const float* __restrict__ hE, const int* __restrict__ eidx,
                 const float* __restrict__ W1, const float* __restrict__ b1,
                 const float* __restrict__ W2, const float* __restrict__ b2,
                 const float* __restrict__ W3, const float* __restrict__ b3)
{
    extern __shared__ float sm[];
    float* As = sm;                       // [KC][LDT]  layer-1 A chunk (k-major)
    float* Bs = As + KC * LDT;            // [KC][HH]   weight chunk
    float* M1 = Bs + KC * HH;             // [HH][LDT]  layer-1 out, transposed
    float* M2 = M1 + HH * LDT;            // [HH][LDT]  layer-2 out, transposed
    int*   s_src = (int*)(M2 + HH * LDT); // [TE]

    const int tid = threadIdx.x;
    const int tx  = tid & 15;             // feature group
    const int ty  = tid >> 4;             // edge-row group
    const size_t e0 = (size_t)blockIdx.x * TE;

    if (tid < TE) s_src[tid] = eidx[e0 + tid];   // row 0 of [2, NE] = src

    float acc[8][8];
#pragma unroll
    for (int i = 0; i < 8; i++)
#pragma unroll
        for (int j = 0; j < 8; j++) acc[i][j] = 0.f;

    // ---------------- layer 1: [TE,256] @ [256,128] ----------------
    for (int kc = 0; kc < KIN; kc += KC) {
        // stage X chunk, transposed to k-major
#pragma unroll
        for (int it = 0; it < 4; it++) {
            int idx = tid + 256 * it;       // 0..1023
            int r = idx >> 3, c4 = idx & 7;
            float4 v = *(const float4*)(hE + (e0 + r) * KIN + kc + c4 * 4);
            As[(c4 * 4 + 0) * LDT + r] = v.x;
            As[(c4 * 4 + 1) * LDT + r] = v.y;
            As[(c4 * 4 + 2) * LDT + r] = v.z;
            As[(c4 * 4 + 3) * LDT + r] = v.w;
        }
        // stage W1 chunk (natural layout)
#pragma unroll
        for (int it = 0; it < 4; it++) {
            int idx = tid + 256 * it;
            int r = idx >> 5, c4 = idx & 31;
            *(float4*)(Bs + r * HH + c4 * 4) =
                *(const float4*)(W1 + (size_t)(kc + r) * HH + c4 * 4);
        }
        __syncthreads();
#pragma unroll
        for (int k = 0; k < KC; k++) {
            float a[8], b[8];
            *(float4*)&a[0] = *(float4*)(As + k * LDT + ty * 8);
            *(float4*)&a[4] = *(float4*)(As + k * LDT + ty * 8 + 4);
#pragma unroll
            for (int j = 0; j < 8; j++) b[j] = Bs[k * HH + tx + 16 * j];
#pragma unroll
            for (int i = 0; i < 8; i++)
#pragma unroll
                for (int j = 0; j < 8; j++)
                    acc[i][j] = fmaf(a[i], b[j], acc[i][j]);
        }
        __syncthreads();
    }
    // bias + relu -> M1 (transposed [feature][edge])
#pragma unroll
    for (int j = 0; j < 8; j++) {
        int col = tx + 16 * j;
        float bb = b1[col];
#pragma unroll
        for (int i = 0; i < 8; i++) {
            M1[col * LDT + ty * 8 + i] = fmaxf(acc[i][j] + bb, 0.f);
            acc[i][j] = 0.f;
        }
    }

    // ---------------- layer 2: [TE,128] @ [128,128] ----------------
    for (int kc = 0; kc < HH; kc += KC) {
#pragma unroll
        for (int it = 0; it < 4; it++) {
            int idx = tid + 256 * it;
            int r = idx >> 5, c4 = idx & 31;
            *(float4*)(Bs + r * HH + c4 * 4) =
                *(const float4*)(W2 + (size_t)(kc + r) * HH + c4 * 4);
        }
        __syncthreads();
#pragma unroll
        for (int k = 0; k < KC; k++) {
            float a[8], b[8];
            *(float4*)&a[0] = *(float4*)(M1 + (kc + k) * LDT + ty * 8);
            *(float4*)&a[4] = *(float4*)(M1 + (kc + k) * LDT + ty * 8 + 4);
#pragma unroll
            for (int j = 0; j < 8; j++) b[j] = Bs[k * HH + tx + 16 * j];
#pragma unroll
            for (int i = 0; i < 8; i++)
#pragma unroll
                for (int j = 0; j < 8; j++)
                    acc[i][j] = fmaf(a[i], b[j], acc[i][j]);
        }
        __syncthreads();
    }
#pragma unroll
    for (int j = 0; j < 8; j++) {
        int col = tx + 16 * j;
        float bb = b2[col];
#pragma unroll
        for (int i = 0; i < 8; i++) {
            M2[col * LDT + ty * 8 + i] = fmaxf(acc[i][j] + bb, 0.f);
            acc[i][j] = 0.f;
        }
    }

    // ---------------- layer 3: [TE,128] @ [128,128] ----------------
    for (int kc = 0; kc < HH; kc += KC) {
#pragma unroll
        for (int it = 0; it < 4; it++) {
            int idx = tid + 256 * it;
            int r = idx >> 5, c4 = idx & 31;
            *(float4*)(Bs + r * HH + c4 * 4) =
                *(const float4*)(W3 + (size_t)(kc + r) * HH + c4 * 4);
        }
        __syncthreads();
#pragma unroll
        for (int k = 0; k < KC; k++) {
            float a[8], b[8];
            *(float4*)&a[0] = *(float4*)(M2 + (kc + k) * LDT + ty * 8);
            *(float4*)&a[4] = *(float4*)(M2 + (kc + k) * LDT + ty * 8 + 4);
#pragma unroll
            for (int j = 0; j < 8; j++) b[j] = Bs[k * HH + tx + 16 * j];
#pragma unroll
            for (int i = 0; i < 8; i++)
#pragma unroll
                for (int j = 0; j < 8; j++)
                    acc[i][j] = fmaf(a[i], b[j], acc[i][j]);
        }
        __syncthreads();
    }

    // epilogue: bias, 1/SCALE, atomic scatter into g_dh[src]
#pragma unroll
    for (int i = 0; i < 8; i++) {
        int s = s_src[ty * 8 + i];
        float* dst = g_dh + (size_t)s * HH;
#pragma unroll
        for (int j = 0; j < 8; j++) {
            int col = tx + 16 * j;
            atomicAdd(dst + col, (acc[i][j] + b3[col]) * SINV);
        }
    }
}

// ---------------------------------------------------------------------------
// Fused node block: h = LN(hV + dh); y = LN(h + relu(h@D1+db1)@D2 + db2)
__global__ __launch_bounds__(256, 1)
void node_kernel(const float* __restrict__ hV,
                 const float* __restrict__ D1, const float* __restrict__ db1,
                 const float* __restrict__ D2, const float* __restrict__ db2,
                 const float* __restrict__ g1, const float* __restrict__ be1,
                 const float* __restrict__ g2, const float* __restrict__ be2,
                 float* __restrict__ out)
{
    extern __shared__ float sm[];
    float* Z  = sm;                    // [TE][LDT]  z / t-chunk (reused) / y
    float* HT = Z + TE * LDT;          // [HH][LDT]  h transposed
    float* Bs = HT + HH * LDT;         // [KC][HH]
    float* s_mu = Bs + KC * HH;        // [TE]
    float* s_rs = s_mu + TE;           // [TE]

    const int tid = threadIdx.x;
    const int tx  = tid & 15;
    const int ty  = tid >> 4;
    const int n0  = blockIdx.x * TE;
    const int nrem = min(TE, NND - n0);

    // z = hV + dh (zero-pad past nrem)
    for (int idx = tid; idx < TE * HH; idx += 256) {
        int r = idx >> 7, c = idx & 127;
        float v = 0.f;
        if (r < nrem) {
            size_t g = (size_t)(n0 + r) * HH + c;
            v = hV[g] + g_dh[g];
        }
        Z[r * LDT + c] = v;
    }
    __syncthreads();

    // LN1 row stats
    if (tid < TE) {
        const float* zr = Z + tid * LDT;
        float s = 0.f;
        for (int c = 0; c < HH; c++) s += zr[c];
        float mu = s * (1.f / HH);
        float v = 0.f;
        for (int c = 0; c < HH; c++) { float d = zr[c] - mu; v += d * d; }
        s_mu[tid] = mu;
        s_rs[tid] = rsqrtf(v * (1.f / HH) + 1e-5f);
    }
    __syncthreads();

    // h = (z-mu)*rs*g1 + be1 -> HT transposed
    for (int idx = tid; idx < TE * HH; idx += 256) {
        int r = idx >> 7, c = idx & 127;
        float hval = (Z[r * LDT + c] - s_mu[r]) * s_rs[r] * g1[c] + be1[c];
        HT[c * LDT + r] = hval;
    }
    __syncthreads();

    float acc2[8][8];
#pragma unroll
    for (int i = 0; i < 8; i++)
#pragma unroll
        for (int j = 0; j < 8; j++) acc2[i][j] = 0.f;

    // FFN, q in chunks of 128: t = relu(h@D1+db1); dh2 += t@D2
    for (int qc = 0; qc < FF; qc += 128) {
        float acc1[8][8];
#pragma unroll
        for (int i = 0; i < 8; i++)
#pragma unroll
            for (int j = 0; j < 8; j++) acc1[i][j] = 0.f;

        for (int kc = 0; kc < HH; kc += KC) {
#pragma unroll
            for (int it = 0; it < 4; it++) {
                int idx = tid + 256 * it;
                int r = idx >> 5, c4 = idx & 31;
                *(float4*)(Bs + r * HH + c4 * 4) =
                    *(const float4*)(D1 + (size_t)(kc + r) * FF + qc + c4 * 4);
            }
            __syncthreads();
#pragma unroll
            for (int k = 0; k < KC; k++) {
                float a[8], b[8];
                *(float4*)&a[0] = *(float4*)(HT + (kc + k) * LDT + ty * 8);
                *(float4*)&a[4] = *(float4*)(HT + (kc + k) * LDT + ty * 8 + 4);
#pragma unroll
                for (int j = 0; j < 8; j++) b[j] = Bs[k * HH + tx + 16 * j];
#pragma unroll
                for (int i = 0; i < 8; i++)
#pragma unroll
                    for (int j = 0; j < 8; j++)
                        acc1[i][j] = fmaf(a[i], b[j], acc1[i][j]);
            }
            __syncthreads();
        }
        // relu(t)+db1 -> Z (reused as t-chunk, transposed [q][row])
#pragma unroll
        for (int j = 0; j < 8; j++) {
            int q = tx + 16 * j;
            float bb = db1[qc + q];
#pragma unroll
            for (int i = 0; i < 8; i++)
                Z[q * LDT + ty * 8 + i] = fmaxf(acc1[i][j] + bb, 0.f);
        }

        for (int kq = 0; kq < 128; kq += KC) {
#pragma unroll
            for (int it = 0; it < 4; it++) {
                int idx = tid + 256 * it;
                int r = idx >> 5, c4 = idx & 31;
                *(float4*)(Bs + r * HH + c4 * 4) =
                    *(const float4*)(D2 + (size_t)(qc + kq + r) * HH + c4 * 4);
            }
            __syncthreads();
#pragma unroll
            for (int k = 0; k < KC; k++) {
                float a[8], b[8];
                *(float4*)&a[0] = *(float4*)(Z + (kq + k) * LDT + ty * 8);
                *(float4*)&a[4] = *(float4*)(Z + (kq + k) * LDT + ty * 8 + 4);
#pragma unroll
                for (int j = 0; j < 8; j++) b[j] = Bs[k * HH + tx + 16 * j];
#pragma unroll
                for (int i = 0; i < 8; i++)
#pragma unroll
                    for (int j = 0; j < 8; j++)
                        acc2[i][j] = fmaf(a[i], b[j], acc2[i][j]);
            }
            __syncthreads();
        }
    }

    // y = h + dh2 + db2 -> Z
#pragma unroll
    for (int j = 0; j < 8; j++) {
        int c = tx + 16 * j;
        float bb = db2[c];
#pragma unroll
        for (int i = 0; i < 8; i++) {
            int r = ty * 8 + i;
            Z[r * LDT + c] = HT[c * LDT + r] + acc2[i][j] + bb;
        }
    }
    __syncthreads();

    // LN2 row stats
    if (tid < TE) {
        const float* zr = Z + tid * LDT;
        float s = 0.f;
        for (int c = 0; c < HH; c++) s += zr[c];
        float mu = s * (1.f / HH);
        float v = 0.f;
        for (int c = 0; c < HH; c++) { float d = zr[c] - mu; v += d * d; }
        s_mu[tid] = mu;
        s_rs[tid] = rsqrtf(v * (1.f / HH) + 1e-5f);
    }
    __syncthreads();

    for (int idx = tid; idx < TE * HH; idx += 256) {
        int r = idx >> 7, c = idx & 127;
        if (r < nrem)
            out[(size_t)(n0 + r) * HH + c] =
                (Z[r * LDT + c] - s_mu[r]) * s_rs[r] * g2[c] + be2[c];
    }
}

// ---------------------------------------------------------------------------
extern "C" void kernel_launch(void* const* d_in, const int* in_sizes, int n_in,
                              void* d_out, int out_size)
{
    const float* hV   = (const float*)d_in[0];
    const float* hE   = (const float*)d_in[1];
    const int*   eidx = (const int*)d_in[2];   // int32 [2, NE]; row 0 = src
    const float* W1  = (const float*)d_in[3];
    const float* b1  = (const float*)d_in[4];
    const float* W2  = (const float*)d_in[5];
    const float* b2  = (const float*)d_in[6];
    const float* W3  = (const float*)d_in[7];
    const float* b3  = (const float*)d_in[8];
    const float* D1  = (const float*)d_in[9];
    const float* db1 = (const float*)d_in[10];
    const float* D2  = (const float*)d_in[11];
    const float* db2 = (const float*)d_in[12];
    const float* g1  = (const float*)d_in[13];
    const float* be1 = (const float*)d_in[14];
    const float* g2  = (const float*)d_in[15];
    const float* be2 = (const float*)d_in[16];
    float* out = (float*)d_out;

    const size_t sm_edge = (size_t)(KC * LDT + KC * HH + 2 * HH * LDT) * 4
                           + TE * sizeof(int);
    const size_t sm_node = (size_t)(TE * LDT + HH * LDT + KC * HH + 2 * TE) * 4;

    cudaFuncSetAttribute(edge_kernel, cudaFuncAttributeMaxDynamicSharedMemorySize,
                         (int)sm_edge);
    cudaFuncSetAttribute(node_kernel, cudaFuncAttributeMaxDynamicSharedMemorySize,
                         (int)sm_node);

    zero_dh_kernel<<<(NND * HH / 4 + 255) / 256, 256>>>();
    edge_kernel<<<NE / TE, 256, sm_edge>>>(hE, eidx, W1, b1, W2, b2, W3, b3);
    node_kernel<<<(NND + TE - 1) / TE, 256, sm_node>>>(hV, D1, db1, D2, db2,
                                                       g1, be1, g2, be2, out);
}

// round 8
// speedup vs baseline: 1.8251x; 1.8251x over previous
#include <cuda_runtime.h>
#include <cuda_bf16.h>
#include <stdint.h>
#include <math.h>

#define NE   800000
#define NND  100000
#define HH   128
#define KIN  256
#define FF   512
#define TE   128
#define KC   32
#define LDT  (TE + 4)
#define SINV (1.0f/30.0f)

// scratch: aggregated messages (51.2 MB) + prepped bf16 split weights (256 KB)
__device__ float g_dh[(size_t)NND * HH];
__device__ __align__(16) unsigned char g_wprep[4 * 65536];

// ===========================================================================
// helpers
// ===========================================================================
__device__ __forceinline__ uint32_t smem_u32(const void* p) {
    uint32_t a;
    asm("{ .reg .u64 t; cvta.to.shared.u64 t, %1; cvt.u32.u64 %0, t; }"
        : "=r"(a) : "l"(p));
    return a;
}

#define LDSM_X4(r0, r1, r2, r3, addr) \
    asm volatile("ldmatrix.sync.aligned.m8n8.x4.shared.b16 {%0,%1,%2,%3}, [%4];" \
        : "=r"(r0), "=r"(r1), "=r"(r2), "=r"(r3) : "r"(addr))

#define LDSM_X4T(r0, r1, r2, r3, addr) \
    asm volatile("ldmatrix.sync.aligned.m8n8.x4.trans.shared.b16 {%0,%1,%2,%3}, [%4];" \
        : "=r"(r0), "=r"(r1), "=r"(r2), "=r"(r3) : "r"(addr))

#define MMA_BF16(d, a, b0, b1) \
    asm volatile("mma.sync.aligned.m16n8k16.row.col.f32.bf16.bf16.f32 " \
        "{%0,%1,%2,%3}, {%4,%5,%6,%7}, {%8,%9}, {%0,%1,%2,%3};" \
        : "+f"((d)[0]), "+f"((d)[1]), "+f"((d)[2]), "+f"((d)[3]) \
        : "r"((a)[0]), "r"((a)[1]), "r"((a)[2]), "r"((a)[3]), "r"(b0), "r"(b1))

#define CP_WAIT(n) asm volatile("cp.async.wait_group %0;" :: "n"(n) : "memory")

// copy one 64KB weight chunk to SMEM (per-thread 16 x 16B) + commit group
__device__ __forceinline__ void cp_w(uint32_t dsts, const unsigned char* src, int tid) {
#pragma unroll
    for (int i = 0; i < 16; i++) {
        uint32_t o = (uint32_t)(tid + 256 * i) * 16u;
        asm volatile("cp.async.cg.shared.global [%0], [%1], 16;"
                     :: "r"(dsts + o), "l"(src + o) : "memory");
    }
    asm volatile("cp.async.commit_group;" ::: "memory");
}

__device__ __forceinline__ uint32_t pack_bf2(float v0, float v1) {
    __nv_bfloat16 h0 = __float2bfloat16(v0), h1 = __float2bfloat16(v1);
    return (uint32_t)__bfloat16_as_ushort(h0) | ((uint32_t)__bfloat16_as_ushort(h1) << 16);
}

// SMEM offsets (bytes from 128-aligned base)
#define OF_SRC  0
#define OF_BIAS 512
#define OF_AHI  2048
#define OF_ALO  34816
#define OF_W0   67584
#define OF_W1   133120
#define SM_EDGE (198656 + 128)

// ===========================================================================
__global__ void zero_dh_kernel() {
    size_t i = (size_t)blockIdx.x * blockDim.x + threadIdx.x;
    if (i < (size_t)NND * HH / 4)
        ((float4*)g_dh)[i] = make_float4(0.f, 0.f, 0.f, 0.f);
}

// Pre-convert weights to bf16 hi/lo in [k][n] slab layout, SW128 swizzled.
// Chunks: 0=W1[k0:128), 1=W1[k128:256), 2=W2, 3=W3.
// Per 64KB chunk: [hi slab n0-63][hi slab n64-127][lo slab n0-63][lo slab n64-127]
__global__ void prep_w_kernel(const float* __restrict__ W1,
                              const float* __restrict__ W2,
                              const float* __restrict__ W3) {
    int t = blockIdx.x * 256 + threadIdx.x;      // 0..65535
    int c  = t >> 14;
    int r  = t & 16383;
    int n  = r & 127;
    int kl = r >> 7;       // k within chunk (row of slab)
    const float* W; int kg;
    if      (c == 0) { W = W1; kg = kl; }
    else if (c == 1) { W = W1; kg = kl + 128; }
    else if (c == 2) { W = W2; kg = kl; }
    else             { W = W3; kg = kl; }
    float w = W[(size_t)kg * 128 + n];
    __nv_bfloat16 hi = __float2bfloat16(w);
    __nv_bfloat16 lo = __float2bfloat16(w - __bfloat162float(hi));
    int slab = n >> 6, nn = n & 63;
    uint32_t off = ((uint32_t)(kl >> 3) << 10) + ((uint32_t)(kl & 7) << 7) + nn * 2;
    off ^= (off >> 3) & 0x70;
    size_t base = (size_t)c * 65536 + (size_t)slab * 16384 + off;
    *(__nv_bfloat16*)(g_wprep + base) = hi;
    *(__nv_bfloat16*)(g_wprep + base + 32768) = lo;
}

// Stage a K=128 activation chunk: fp32 -> bf16 hi/lo into SW128 [m][k] slabs.
__device__ __forceinline__ void stage_A(uint8_t* smb, const float* __restrict__ hE,
                                        size_t e0, int kc, int tid) {
#pragma unroll
    for (int it = 0; it < 16; it++) {
        int idx = tid + 256 * it;           // 0..4095 (128 rows x 32 float4)
        int r = idx >> 5, c4 = idx & 31;
        float4 v = *(const float4*)(hE + (e0 + r) * KIN + kc + c4 * 4);
        __nv_bfloat16 h0 = __float2bfloat16(v.x), h1 = __float2bfloat16(v.y);
        __nv_bfloat16 h2 = __float2bfloat16(v.z), h3 = __float2bfloat16(v.w);
        __nv_bfloat16 l0 = __float2bfloat16(v.x - __bfloat162float(h0));
        __nv_bfloat16 l1 = __float2bfloat16(v.y - __bfloat162float(h1));
        __nv_bfloat16 l2 = __float2bfloat16(v.z - __bfloat162float(h2));
        __nv_bfloat16 l3 = __float2bfloat16(v.w - __bfloat162float(h3));
        uint32_t hA = (uint32_t)__bfloat16_as_ushort(h0) | ((uint32_t)__bfloat16_as_ushort(h1) << 16);
        uint32_t hB = (uint32_t)__bfloat16_as_ushort(h2) | ((uint32_t)__bfloat16_as_ushort(h3) << 16);
        uint32_t lA = (uint32_t)__bfloat16_as_ushort(l0) | ((uint32_t)__bfloat16_as_ushort(l1) << 16);
        uint32_t lB = (uint32_t)__bfloat16_as_ushort(l2) | ((uint32_t)__bfloat16_as_ushort(l3) << 16);
        uint32_t off = ((uint32_t)(r >> 3) << 10) + ((uint32_t)(r & 7) << 7) + ((uint32_t)(c4 & 15) << 3);
        off ^= (off >> 3) & 0x70;
        uint32_t slab = (uint32_t)(c4 >> 4) * 16384;
        *(uint2*)(smb + OF_AHI + slab + off) = make_uint2(hA, hB);
        *(uint2*)(smb + OF_ALO + slab + off) = make_uint2(lA, lB);
    }
}

// One K=128 chunk of bf16x3 MMAs: acc += A*W (3 split passes).
__device__ __forceinline__ void mma_chunk(float (*acc)[8][4], uint32_t ahi, uint32_t alo,
                                          uint32_t wb, int warpM, int warpN, int lane) {
#pragma unroll
    for (int pass = 0; pass < 3; pass++) {
        uint32_t ab = (pass == 2) ? alo : ahi;
        uint32_t bb = wb + ((pass == 1) ? 32768u : 0u) + (uint32_t)warpN * 16384u;
#pragma unroll
        for (int s = 0; s < 8; s++) {
            uint32_t a[2][4];
#pragma unroll
            for (int mi = 0; mi < 2; mi++) {
                int row = warpM * 32 + mi * 16 + (lane & 15);
                uint32_t off = ((uint32_t)(row >> 3) << 10) + ((uint32_t)(row & 7) << 7)
                             + (uint32_t)((s & 3) * 32 + ((lane >> 4) << 4));
                off ^= (off >> 3) & 0x70;
                LDSM_X4(a[mi][0], a[mi][1], a[mi][2], a[mi][3],
                        ab + (uint32_t)(s >> 2) * 16384u + off);
            }
            uint32_t b[4][4];
#pragma unroll
            for (int bt = 0; bt < 4; bt++) {
                int k = s * 16 + (lane & 15);
                uint32_t off = ((uint32_t)(k >> 3) << 10) + ((uint32_t)(k & 7) << 7)
                             + (uint32_t)(bt * 32 + ((lane >> 4) << 4));
                off ^= (off >> 3) & 0x70;
                LDSM_X4T(b[bt][0], b[bt][1], b[bt][2], b[bt][3], bb + off);
            }
#pragma unroll
            for (int mi = 0; mi < 2; mi++)
#pragma unroll
                for (int nt = 0; nt < 8; nt++)
                    MMA_BF16(acc[mi][nt], a[mi], b[nt >> 1][(nt & 1) * 2],
                             b[nt >> 1][(nt & 1) * 2 + 1]);
        }
    }
}

// Layer epilogue: relu(acc+bias) -> split hi/lo -> A slabs ([m][k], k=this layer's n).
// Zeros acc for the next layer.
__device__ __forceinline__ void epi_act(float (*acc)[8][4], uint8_t* smb,
                                        const float* bias, int warpM, int warpN, int lane) {
    uint32_t slab = (uint32_t)warpN * 16384u;
#pragma unroll
    for (int mi = 0; mi < 2; mi++) {
#pragma unroll
        for (int nt = 0; nt < 8; nt++) {
            int r0 = warpM * 32 + mi * 16 + (lane >> 2);
            int kk = nt * 8 + (lane & 3) * 2;
            int n  = warpN * 64 + kk;
            float b0v = bias[n], b1v = bias[n + 1];
#pragma unroll
            for (int hh = 0; hh < 2; hh++) {
                int r = r0 + hh * 8;
                float v0 = fmaxf(acc[mi][nt][hh * 2 + 0] + b0v, 0.f);
                float v1 = fmaxf(acc[mi][nt][hh * 2 + 1] + b1v, 0.f);
                __nv_bfloat16 h0 = __float2bfloat16(v0), h1 = __float2bfloat16(v1);
                float f0 = __bfloat162float(h0), f1 = __bfloat162float(h1);
                uint32_t hp = (uint32_t)__bfloat16_as_ushort(h0)
                            | ((uint32_t)__bfloat16_as_ushort(h1) << 16);
                uint32_t lp = pack_bf2(v0 - f0, v1 - f1);
                uint32_t off = ((uint32_t)(r >> 3) << 10) + ((uint32_t)(r & 7) << 7)
                             + (uint32_t)kk * 2;
                off ^= (off >> 3) & 0x70;
                *(uint32_t*)(smb + OF_AHI + slab + off) = hp;
                *(uint32_t*)(smb + OF_ALO + slab + off) = lp;
            }
            acc[mi][nt][0] = 0.f; acc[mi][nt][1] = 0.f;
            acc[mi][nt][2] = 0.f; acc[mi][nt][3] = 0.f;
        }
    }
}

// ===========================================================================
// Edge kernel: fused 3-layer MLP on HMMA (bf16x3) + vector-red scatter
// ===========================================================================
__global__ __launch_bounds__(256, 1)
void edge_mma_kernel(const float* __restrict__ hE, const int* __restrict__ eidx,
                     const float* __restrict__ b1, const float* __restrict__ b2,
                     const float* __restrict__ b3)
{
    extern __shared__ __align__(16) uint8_t sm8[];
    uint32_t sbr = smem_u32(sm8);
    uint32_t sb  = (sbr + 127u) & ~127u;
    uint8_t* smb = sm8 + (sb - sbr);

    const int tid = threadIdx.x, wid = tid >> 5, lane = tid & 31;
    const int warpM = wid & 3, warpN = wid >> 2;
    const size_t e0 = (size_t)blockIdx.x * TE;

    if (tid < 128) {
        ((int*)(smb + OF_SRC))[tid] = eidx[e0 + tid];       // row 0 = src
        float* bs = (float*)(smb + OF_BIAS);
        bs[tid] = b1[tid]; bs[128 + tid] = b2[tid]; bs[256 + tid] = b3[tid];
    }

    cp_w(sb + OF_W0, g_wprep, tid);              // G0: W1 chunk k0-127
    cp_w(sb + OF_W1, g_wprep + 65536, tid);      // G1: W1 chunk k128-255

    stage_A(smb, hE, e0, 0, tid);
    CP_WAIT(1);
    __syncthreads();

    float acc[2][8][4];
#pragma unroll
    for (int mi = 0; mi < 2; mi++)
#pragma unroll
        for (int nt = 0; nt < 8; nt++)
#pragma unroll
            for (int q = 0; q < 4; q++) acc[mi][nt][q] = 0.f;

    const float* bias_sm = (const float*)(smb + OF_BIAS);

    // ---- layer 1, chunk 0 ----
    mma_chunk(acc, sb + OF_AHI, sb + OF_ALO, sb + OF_W0, warpM, warpN, lane);
    __syncthreads();

    // ---- layer 1, chunk 1 ----
    cp_w(sb + OF_W0, g_wprep + 131072, tid);     // G2: W2 into buf0
    stage_A(smb, hE, e0, 128, tid);
    CP_WAIT(1);                                  // G1 done (G2 may pend)
    __syncthreads();
    mma_chunk(acc, sb + OF_AHI, sb + OF_ALO, sb + OF_W1, warpM, warpN, lane);
    __syncthreads();

    epi_act(acc, smb, bias_sm, warpM, warpN, lane);
    cp_w(sb + OF_W1, g_wprep + 196608, tid);     // G3: W3 into buf1
    CP_WAIT(1);                                  // G2 done
    __syncthreads();

    // ---- layer 2 ----
    mma_chunk(acc, sb + OF_AHI, sb + OF_ALO, sb + OF_W0, warpM, warpN, lane);
    __syncthreads();
    epi_act(acc, smb, bias_sm + 128, warpM, warpN, lane);
    CP_WAIT(0);                                  // G3 done
    __syncthreads();

    // ---- layer 3 ----
    mma_chunk(acc, sb + OF_AHI, sb + OF_ALO, sb + OF_W1, warpM, warpN, lane);

    // scatter epilogue: (acc + b3) * SINV -> red.v2 into g_dh[src]
    const int* s_src = (const int*)(smb + OF_SRC);
    const float* b3s = bias_sm + 256;
#pragma unroll
    for (int mi = 0; mi < 2; mi++) {
#pragma unroll
        for (int nt = 0; nt < 8; nt++) {
            int r0 = warpM * 32 + mi * 16 + (lane >> 2);
            int n  = warpN * 64 + nt * 8 + (lane & 3) * 2;
            float bb0 = b3s[n], bb1 = b3s[n + 1];
#pragma unroll
            for (int hh = 0; hh < 2; hh++) {
                int r = r0 + hh * 8;
                int srcn = s_src[r];
                float v0 = (acc[mi][nt][hh * 2 + 0] + bb0) * SINV;
                float v1 = (acc[mi][nt][hh * 2 + 1] + bb1) * SINV;
                float* dst = g_dh + (size_t)srcn * HH + n;
                asm volatile("red.global.add.v2.f32 [%0], {%1, %2};"
                             :: "l"(dst), "f"(v0), "f"(v1) : "memory");
            }
        }
    }
}

// ===========================================================================
// Node kernel (unchanged, validated): h=LN(hV+dh); y=LN(h + FFN(h))
// ===========================================================================
__global__ __launch_bounds__(256, 1)
void node_kernel(const float* __restrict__ hV,
                 const float* __restrict__ D1, const float* __restrict__ db1,
                 const float* __restrict__ D2, const float* __restrict__ db2,
                 const float* __restrict__ g1, const float* __restrict__ be1,
                 const float* __restrict__ g2, const float* __restrict__ be2,
                 float* __restrict__ out)
{
    extern __shared__ float sm[];
    float* Z  = sm;
    float* HT = Z + TE * LDT;
    float* Bs = HT + HH * LDT;
    float* s_mu = Bs + KC * HH;
    float* s_rs = s_mu + TE;

    const int tid = threadIdx.x;
    const int tx  = tid & 15;
    const int ty  = tid >> 4;
    const int n0  = blockIdx.x * TE;
    const int nrem = min(TE, NND - n0);

    for (int idx = tid; idx < TE * HH; idx += 256) {
        int r = idx >> 7, c = idx & 127;
        float v = 0.f;
        if (r < nrem) {
            size_t g = (size_t)(n0 + r) * HH + c;
            v = hV[g] + g_dh[g];
        }
        Z[r * LDT + c] = v;
    }
    __syncthreads();

    if (tid < TE) {
        const float* zr = Z + tid * LDT;
        float s = 0.f;
        for (int c = 0; c < HH; c++) s += zr[c];
        float mu = s * (1.f / HH);
        float v = 0.f;
        for (int c = 0; c < HH; c++) { float d = zr[c] - mu; v += d * d; }
        s_mu[tid] = mu;
        s_rs[tid] = rsqrtf(v * (1.f / HH) + 1e-5f);
    }
    __syncthreads();

    for (int idx = tid; idx < TE * HH; idx += 256) {
        int r = idx >> 7, c = idx & 127;
        float hval = (Z[r * LDT + c] - s_mu[r]) * s_rs[r] * g1[c] + be1[c];
        HT[c * LDT + r] = hval;
    }
    __syncthreads();

    float acc2[8][8];
#pragma unroll
    for (int i = 0; i < 8; i++)
#pragma unroll
        for (int j = 0; j < 8; j++) acc2[i][j] = 0.f;

    for (int qc = 0; qc < FF; qc += 128) {
        float acc1[8][8];
#pragma unroll
        for (int i = 0; i < 8; i++)
#pragma unroll
            for (int j = 0; j < 8; j++) acc1[i][j] = 0.f;

        for (int kc = 0; kc < HH; kc += KC) {
#pragma unroll
            for (int it = 0; it < 4; it++) {
                int idx = tid + 256 * it;
                int r = idx >> 5, c4 = idx & 31;
                *(float4*)(Bs + r * HH + c4 * 4) =
                    *(const float4*)(D1 + (size_t)(kc + r) * FF + qc + c4 * 4);
            }
            __syncthreads();
#pragma unroll
            for (int k = 0; k < KC; k++) {
                float a[8], b[8];
                *(float4*)&a[0] = *(float4*)(HT + (kc + k) * LDT + ty * 8);
                *(float4*)&a[4] = *(float4*)(HT + (kc + k) * LDT + ty * 8 + 4);
#pragma unroll
                for (int j = 0; j < 8; j++) b[j] = Bs[k * HH + tx + 16 * j];
#pragma unroll
                for (int i = 0; i < 8; i++)
#pragma unroll
                    for (int j = 0; j < 8; j++)
                        acc1[i][j] = fmaf(a[i], b[j], acc1[i][j]);
            }
            __syncthreads();
        }
#pragma unroll
        for (int j = 0; j < 8; j++) {
            int q = tx + 16 * j;
            float bb = db1[qc + q];
#pragma unroll
            for (int i = 0; i < 8; i++)
                Z[q * LDT + ty * 8 + i] = fmaxf(acc1[i][j] + bb, 0.f);
        }

        for (int kq = 0; kq < 128; kq += KC) {
#pragma unroll
            for (int it = 0; it < 4; it++) {
                int idx = tid + 256 * it;
                int r = idx >> 5, c4 = idx & 31;
                *(float4*)(Bs + r * HH + c4 * 4) =
                    *(const float4*)(D2 + (size_t)(qc + kq + r) * HH + c4 * 4);
            }
            __syncthreads();
#pragma unroll
            for (int k = 0; k < KC; k++) {
                float a[8], b[8];
                *(float4*)&a[0] = *(float4*)(Z + (kq + k) * LDT + ty * 8);
                *(float4*)&a[4] = *(float4*)(Z + (kq + k) * LDT + ty * 8 + 4);
#pragma unroll
                for (int j = 0; j < 8; j++) b[j] = Bs[k * HH + tx + 16 * j];
#pragma unroll
                for (int i = 0; i < 8; i++)
#pragma unroll
                    for (int j = 0; j < 8; j++)
                        acc2[i][j] = fmaf(a[i], b[j], acc2[i][j]);
            }
            __syncthreads();
        }
    }

#pragma unroll
    for (int j = 0; j < 8; j++) {
        int c = tx + 16 * j;
        float bb = db2[c];
#pragma unroll
        for (int i = 0; i < 8; i++) {
            int r = ty * 8 + i;
            Z[r * LDT + c] = HT[c * LDT + r] + acc2[i][j] + bb;
        }
    }
    __syncthreads();

    if (tid < TE) {
        const float* zr = Z + tid * LDT;
        float s = 0.f;
        for (int c = 0; c < HH; c++) s += zr[c];
        float mu = s * (1.f / HH);
        float v = 0.f;
        for (int c = 0; c < HH; c++) { float d = zr[c] - mu; v += d * d; }
        s_mu[tid] = mu;
        s_rs[tid] = rsqrtf(v * (1.f / HH) + 1e-5f);
    }
    __syncthreads();

    for (int idx = tid; idx < TE * HH; idx += 256) {
        int r = idx >> 7, c = idx & 127;
        if (r < nrem)
            out[(size_t)(n0 + r) * HH + c] =
                (Z[r * LDT + c] - s_mu[r]) * s_rs[r] * g2[c] + be2[c];
    }
}

// ===========================================================================
extern "C" void kernel_launch(void* const* d_in, const int* in_sizes, int n_in,
                              void* d_out, int out_size)
{
    const float* hV   = (const float*)d_in[0];
    const float* hE   = (const float*)d_in[1];
    const int*   eidx = (const int*)d_in[2];   // int32 [2, NE]; row 0 = src
    const float* W1  = (const float*)d_in[3];
    const float* b1  = (const float*)d_in[4];
    const float* W2  = (const float*)d_in[5];
    const float* b2  = (const float*)d_in[6];
    const float* W3  = (const float*)d_in[7];
    const float* b3  = (const float*)d_in[8];
    const float* D1  = (const float*)d_in[9];
    const float* db1 = (const float*)d_in[10];
    const float* D2  = (const float*)d_in[11];
    const float* db2 = (const float*)d_in[12];
    const float* g1  = (const float*)d_in[13];
    const float* be1 = (const float*)d_in[14];
    const float* g2  = (const float*)d_in[15];
    const float* be2 = (const float*)d_in[16];
    float* out = (float*)d_out;

    const size_t sm_node = (size_t)(TE * LDT + HH * LDT + KC * HH + 2 * TE) * 4;

    cudaFuncSetAttribute(edge_mma_kernel, cudaFuncAttributeMaxDynamicSharedMemorySize,
                         SM_EDGE);
    cudaFuncSetAttribute(node_kernel, cudaFuncAttributeMaxDynamicSharedMemorySize,
                         (int)sm_node);

    zero_dh_kernel<<<(NND * HH / 4 + 255) / 256, 256>>>();
    prep_w_kernel<<<256, 256>>>(W1, W2, W3);
    edge_mma_kernel<<<NE / TE, 256, SM_EDGE>>>(hE, eidx, b1, b2, b3);
    node_kernel<<<(NND + TE - 1) / TE, 256, sm_node>>>(hV, D1, db1, D2, db2,
                                                       g1, be1, g2, be2, out);
}